// round 6
// baseline (speedup 1.0000x reference)
#include <cuda_runtime.h>
#include <math.h>

// FeedForwardQuantum fused v6 — occupancy-first:
//   out = cos(relu(x@W1 + b1) + theta) @ W2 + b2
// Key changes vs v5: W1 tiled through smem per-chunk (no 64KB table),
// ROWS=64/grid=512, regs capped for 4 CTAs/SM (32 warps).
// GEMM1: thread=(p rows p/p+32, qh q-half, h d-quarter of 32d chunk):
//   per 4d step: 2 x-LDS + 8 w-LDS(broadcast) : 32 FFMA2.
// Double-buffered x AND W1 chunks, register prefetch, 1 sync/chunk.
// 4-way h-combine via 2-plane tree. GEMM2: W2 in regs, 2-row unroll.

#define DDIM 1024
#define QDIM 16
#define ROWS 64
#define NTH 256
#define NCH 32
#define XSTR 36
#define PSTR 17
#define ZSTR 36
#define WCH 512            // floats per pair-interleaved W1 chunk (32d x 16q)

typedef unsigned long long u64;

__device__ __forceinline__ void ffma2(u64 &d, u64 a, u64 b) {
    asm("fma.rn.f32x2 %0, %1, %2, %0;" : "+l"(d) : "l"(a), "l"(b));
}
__device__ __forceinline__ float2 unpk(u64 v) {
    float2 f;
    asm("mov.b64 {%0,%1}, %2;" : "=f"(f.x), "=f"(f.y) : "l"(v));
    return f;
}
__device__ __forceinline__ u64 pk(float x, float y) {
    u64 v;
    asm("mov.b64 %0, {%1,%2};" : "=l"(v) : "f"(x), "f"(y));
    return v;
}

__global__ void __launch_bounds__(NTH, 4)
ffq_v6(const float* __restrict__ x, const float* __restrict__ W1,
       const float* __restrict__ b1, const float* __restrict__ theta,
       const float* __restrict__ W2, const float* __restrict__ b2,
       float* __restrict__ out, int nRows)
{
    extern __shared__ float sm[];
    float* w1c0 = sm;                      // 512
    float* w1c1 = w1c0 + WCH;              // 512
    float* xb0  = w1c1 + WCH;              // 64*36 = 2304
    float* xb1  = xb0 + ROWS * XSTR;       // 2304
    float* b1s  = xb1 + ROWS * XSTR;       // 16
    float* ths  = b1s + QDIM;              // 16
    // aliases (used after the main loop only):
    float* pl0 = xb0;                      // 64*17 = 1088
    float* pl1 = xb0 + ROWS * PSTR;        // 1088 (fits in xb0's 2304)
    float* zar = xb1;                      // 64*36 = 2304 (z duplicated)

    const int tid  = threadIdx.x;
    const int row0 = blockIdx.x * ROWS;

    if (tid < QDIM) { b1s[tid] = b1[tid]; ths[tid] = theta[tid]; }

    // ---- GEMM1 ownership ----
    const int p  = tid & 31;               // rows p, p+32
    const int qh = (tid >> 5) & 1;         // q half (8 q)
    const int h  = tid >> 6;               // d quarter of chunk (8 d)

    // ---- x staging: thread owns row srow, cols [scol, scol+8) of each chunk
    const int srow = tid >> 2;
    const int scol = (tid & 3) * 8;
    int gr = row0 + srow; if (gr >= nRows) gr = nRows - 1;
    const float* gpx = x + (size_t)gr * DDIM + scol;

    // ---- W1 staging: thread owns q = tid&15, d-pair block bb = tid>>4
    // loads W1[(ch*32 + 2bb + pp)*16 + q], stores w1c[32bb + 2q + pp]
    const int wq = tid & 15;
    const int wb = tid >> 4;               // 0..15
    const float* gpw = W1 + (size_t)(2 * wb) * QDIM + wq;
    const int wsts = 32 * wb + 2 * wq;

    u64 acc[16];                           // [row(2)][q(8)]
#pragma unroll
    for (int i = 0; i < 16; i++) acc[i] = 0ULL;

    // prologue: chunk 0
    float4 pxa = *reinterpret_cast<const float4*>(gpx);
    float4 pxb = *reinterpret_cast<const float4*>(gpx + 4);
    float  pw0 = gpw[0];
    float  pw1 = gpw[QDIM];
    *reinterpret_cast<float4*>(xb0 + srow * XSTR + scol)     = pxa;
    *reinterpret_cast<float4*>(xb0 + srow * XSTR + scol + 4) = pxb;
    w1c0[wsts]     = pw0;
    w1c0[wsts + 1] = pw1;
    __syncthreads();

    for (int ch = 0; ch < NCH; ch++) {
        float* xc = (ch & 1) ? xb1 : xb0;
        float* xn = (ch & 1) ? xb0 : xb1;
        float* wc = (ch & 1) ? w1c1 : w1c0;
        float* wn = (ch & 1) ? w1c0 : w1c1;

        if (ch + 1 < NCH) {
            int dd = (ch + 1) * 32;
            pxa = *reinterpret_cast<const float4*>(gpx + dd);
            pxb = *reinterpret_cast<const float4*>(gpx + dd + 4);
            pw0 = gpw[(size_t)dd * QDIM];
            pw1 = gpw[(size_t)(dd + 1) * QDIM];
        }

        const float* xr0 = xc + p * XSTR + 8 * h;
        const float* xr1 = xr0 + 32 * XSTR;
#pragma unroll
        for (int s = 0; s < 2; s++) {
            ulonglong2 x0 = *reinterpret_cast<const ulonglong2*>(xr0 + 4 * s);
            ulonglong2 x1 = *reinterpret_cast<const ulonglong2*>(xr1 + 4 * s);
            const float* w0 = wc + (4 * h + 2 * s) * 32 + 16 * qh;      // d-pair blk 0
            const float* w1b = w0 + 32;                                 // d-pair blk 1
#pragma unroll
            for (int m = 0; m < 4; m++) {
                ulonglong2 wA = *reinterpret_cast<const ulonglong2*>(w0 + 4 * m);
                ffma2(acc[2 * m],     x0.x, wA.x);
                ffma2(acc[2 * m + 1], x0.x, wA.y);
                ffma2(acc[8 + 2 * m], x1.x, wA.x);
                ffma2(acc[9 + 2 * m], x1.x, wA.y);
                ulonglong2 wB = *reinterpret_cast<const ulonglong2*>(w1b + 4 * m);
                ffma2(acc[2 * m],     x0.y, wB.x);
                ffma2(acc[2 * m + 1], x0.y, wB.y);
                ffma2(acc[8 + 2 * m], x1.y, wB.x);
                ffma2(acc[9 + 2 * m], x1.y, wB.y);
            }
        }

        if (ch + 1 < NCH) {
            *reinterpret_cast<float4*>(xn + srow * XSTR + scol)     = pxa;
            *reinterpret_cast<float4*>(xn + srow * XSTR + scol + 4) = pxb;
            wn[wsts]     = pw0;
            wn[wsts + 1] = pw1;
        }
        __syncthreads();
    }

    // ---- 4-way h combine via 2-plane tree, activation, z-dup ----
    float hv[16];
#pragma unroll
    for (int i = 0; i < 16; i++) {
        float2 a = unpk(acc[i]);
        hv[i] = a.x + a.y;
    }
    if (h == 1 || h == 3) {
        float* pl = (h == 1) ? pl0 : pl1;
#pragma unroll
        for (int j = 0; j < 8; j++) {
            pl[p * PSTR + 8 * qh + j]        = hv[j];
            pl[(p + 32) * PSTR + 8 * qh + j] = hv[8 + j];
        }
    }
    __syncthreads();
    if (h == 0) {
#pragma unroll
        for (int j = 0; j < 8; j++) {
            hv[j]     += pl0[p * PSTR + 8 * qh + j];
            hv[8 + j] += pl0[(p + 32) * PSTR + 8 * qh + j];
        }
    } else if (h == 2) {
#pragma unroll
        for (int j = 0; j < 8; j++) {
            pl1[p * PSTR + 8 * qh + j]        += hv[j];
            pl1[(p + 32) * PSTR + 8 * qh + j] += hv[8 + j];
        }
    }
    __syncthreads();
    if (h == 0) {
#pragma unroll
        for (int j = 0; j < 8; j++) {
            int q = 8 * qh + j;
            float v0 = hv[j] + pl1[p * PSTR + q] + b1s[q];
            v0 = fmaxf(v0, 0.0f) + ths[q];
            float z0 = __cosf(v0);
            zar[p * ZSTR + 2 * q]     = z0;
            zar[p * ZSTR + 2 * q + 1] = z0;
            float v1 = hv[8 + j] + pl1[(p + 32) * PSTR + q] + b1s[q];
            v1 = fmaxf(v1, 0.0f) + ths[q];
            float z1 = __cosf(v1);
            zar[(p + 32) * ZSTR + 2 * q]     = z1;
            zar[(p + 32) * ZSTR + 2 * q + 1] = z1;
        }
    }
    __syncthreads();

    // ---- GEMM2: W2 in regs, z broadcast LDS, 2-row unroll, STG.128 ----
    const int dcol = 4 * tid;
    ulonglong2 w2r[QDIM];
#pragma unroll
    for (int q = 0; q < QDIM; q++)
        w2r[q] = *reinterpret_cast<const ulonglong2*>(W2 + q * DDIM + dcol);

    float4 b2v = *reinterpret_cast<const float4*>(b2 + dcol);
    const u64 b2p0 = pk(b2v.x, b2v.y);
    const u64 b2p1 = pk(b2v.z, b2v.w);

    for (int rr = 0; rr < ROWS; rr += 2) {
        u64 a0 = b2p0, a1 = b2p1, c0 = b2p0, c1 = b2p1;
        const float* z0 = zar + rr * ZSTR;
        const float* z1 = z0 + ZSTR;
#pragma unroll
        for (int m = 0; m < 8; m++) {
            ulonglong2 zd0 = *reinterpret_cast<const ulonglong2*>(z0 + 4 * m);
            ulonglong2 zd1 = *reinterpret_cast<const ulonglong2*>(z1 + 4 * m);
            ffma2(a0, zd0.x, w2r[2 * m].x);
            ffma2(a1, zd0.x, w2r[2 * m].y);
            ffma2(a0, zd0.y, w2r[2 * m + 1].x);
            ffma2(a1, zd0.y, w2r[2 * m + 1].y);
            ffma2(c0, zd1.x, w2r[2 * m].x);
            ffma2(c1, zd1.x, w2r[2 * m].y);
            ffma2(c0, zd1.y, w2r[2 * m + 1].x);
            ffma2(c1, zd1.y, w2r[2 * m + 1].y);
        }
        int go = row0 + rr;
        if (go < nRows) {
            float2 lo = unpk(a0), hi = unpk(a1);
            *reinterpret_cast<float4*>(out + (size_t)go * DDIM + dcol) =
                make_float4(lo.x, lo.y, hi.x, hi.y);
        }
        if (go + 1 < nRows) {
            float2 lo = unpk(c0), hi = unpk(c1);
            *reinterpret_cast<float4*>(out + (size_t)(go + 1) * DDIM + dcol) =
                make_float4(lo.x, lo.y, hi.x, hi.y);
        }
    }
}

extern "C" void kernel_launch(void* const* d_in, const int* in_sizes, int n_in,
                              void* d_out, int out_size) {
    const float* x     = (const float*)d_in[0];
    const float* W1    = (const float*)d_in[1];
    const float* b1    = (const float*)d_in[2];
    const float* theta = (const float*)d_in[3];
    const float* W2    = (const float*)d_in[4];
    const float* b2    = (const float*)d_in[5];
    float* out = (float*)d_out;

    int nRows = in_sizes[0] / DDIM;                    // 32768
    int grid  = (nRows + ROWS - 1) / ROWS;             // 512

    size_t smem = (size_t)(2 * WCH + 2 * ROWS * XSTR + 2 * QDIM) * sizeof(float);
    // ~22.6 KB dynamic smem -> no attribute needed

    ffq_v6<<<grid, NTH, smem>>>(x, W1, b1, theta, W2, b2, out, nRows);
}